// round 6
// baseline (speedup 1.0000x reference)
#include <cuda_runtime.h>
#include <cuda_fp16.h>
#include <cstdint>

// ============================================================================
// GraphConvolutionSparse: out = adj @ (inputs @ W)
//   inputs [16384, 512] f32, adj [16384, 16384] f32, W [512, 128] f32
//
// tcgen05 is unavailable (harness PTX .target = sm_103, 'a'-features rejected)
// so this uses sm_80-class ldmatrix + mma.sync.m16n8k16 (fp16 in, fp32 accum).
//   GEMM1: xT[n][m] = (inputs @ W)[m][n]   fp16, stored to __device__ scratch
//   GEMM2: out = adj @ x  with B = xT (K-major [128, 16384])
// Both GEMMs: CTA tile 128x128, K-tile 64, 8 warps (32x64 warp tiles),
// 2-stage smem double buffer, fp32->fp16 conversion during staging.
// ============================================================================

#define N_ROWS 16384
#define D_IN   512
#define D_OUT  128

#define MT 128
#define NT 128
#define KT 64
#define STAGE_BYTES (2 * 128 * 128)          // A 16KB fp16 + B 16KB fp16
#define SMEM_TOTAL  (2 * STAGE_BYTES)        // 64 KB

__device__ unsigned short g_xT[D_OUT * N_ROWS];   // x transposed, fp16 bits

// ---------------- helpers ----------------
static __device__ __forceinline__ uint32_t smem_u32(const void* p) {
    uint32_t a;
    asm("{ .reg .u64 t; cvta.to.shared.u64 t, %1; cvt.u32.u64 %0, t; }"
        : "=r"(a) : "l"(p));
    return a;
}
static __device__ __forceinline__ uint32_t pack2(float lo, float hi) {
    __half2 h = __floats2half2_rn(lo, hi);
    return *reinterpret_cast<uint32_t*>(&h);
}
static __device__ __forceinline__ void sts64(uint32_t a, uint32_t u0, uint32_t u1) {
    asm volatile("st.shared.v2.b32 [%0], {%1,%2};" :: "r"(a), "r"(u0), "r"(u1) : "memory");
}
static __device__ __forceinline__ void sts128(uint32_t a, uint4 v) {
    asm volatile("st.shared.v4.b32 [%0], {%1,%2,%3,%4};"
                 :: "r"(a), "r"(v.x), "r"(v.y), "r"(v.z), "r"(v.w) : "memory");
}
static __device__ __forceinline__ void sts16(uint32_t a, unsigned short h) {
    asm volatile("st.shared.u16 [%0], %1;" :: "r"(a), "h"(h) : "memory");
}
static __device__ __forceinline__ void ldsm_x4(uint32_t* r, uint32_t addr) {
    asm volatile("ldmatrix.sync.aligned.m8n8.x4.shared.b16 {%0,%1,%2,%3}, [%4];"
                 : "=r"(r[0]), "=r"(r[1]), "=r"(r[2]), "=r"(r[3]) : "r"(addr));
}
static __device__ __forceinline__ void mma16816(float* c, const uint32_t* a,
                                                uint32_t b0, uint32_t b1) {
    asm volatile(
        "mma.sync.aligned.m16n8k16.row.col.f32.f16.f16.f32 "
        "{%0,%1,%2,%3}, {%4,%5,%6,%7}, {%8,%9}, {%0,%1,%2,%3};"
        : "+f"(c[0]), "+f"(c[1]), "+f"(c[2]), "+f"(c[3])
        : "r"(a[0]), "r"(a[1]), "r"(a[2]), "r"(a[3]), "r"(b0), "r"(b1));
}

// ============================================================================
// Unified GEMM. G1=true : B from W fp32 [K,128], epilogue -> g_xT (fp16, transposed)
//               G1=false: B from g_xT fp16 [128,16384], epilogue -> Out f32 [*,128]
// ============================================================================
template <bool G1>
__global__ void __launch_bounds__(256, 1)
gcn_gemm(const float* __restrict__ A, const float* __restrict__ W,
         float* __restrict__ Out, int K, int lda)
{
    extern __shared__ char smem[];
    const uint32_t sb = smem_u32(smem);
    const int tid = threadIdx.x;
    const int lane = tid & 31;
    const int wid = tid >> 5;
    const int m0 = blockIdx.x * MT;
    const int warpM = (wid & 3) * 32;     // 4 warps along M
    const int warpN = (wid >> 2) * 64;    // 2 warps along N
    const int iters = K / KT;

    // ---- staging registers ----
    float4 af[8];      // A tile: 128 rows x 64 f32 -> per thread 8 float4
    uint4  bx[4];      // G2 B tile: 128 rows x 64 fp16 -> per thread 4 uint4
    float4 bw[8];      // G1 B source: W rows (transposed gather)

    // A staging geometry: thread -> (msub = tid>>4, kq = tid&15)
    const int msub = tid >> 4;
    const int kq   = tid & 15;
    // G2 B staging: thread -> (n = tid>>1, h = tid&1)
    const int bn = tid >> 1;
    const int bh = tid & 1;
    // G1 B staging: thread -> (nq = (tid&31)*4, kk = tid>>5)
    const int nq = (tid & 31) * 4;
    const int kk = tid >> 5;

    auto load_regs = [&](int i) {
        const long k0 = (long)i * KT;
        #pragma unroll
        for (int j = 0; j < 8; j++) {
            const int m = msub + 16 * j;
            af[j] = *reinterpret_cast<const float4*>(A + (long)(m0 + m) * lda + k0 + kq * 4);
        }
        if constexpr (G1) {
            #pragma unroll
            for (int j = 0; j < 8; j++) {
                const long k = k0 + kk + 8 * j;
                bw[j] = *reinterpret_cast<const float4*>(W + k * 128 + nq);
            }
        } else {
            const unsigned short* src = g_xT + (long)bn * N_ROWS + k0 + bh * 32;
            #pragma unroll
            for (int j = 0; j < 4; j++)
                bx[j] = *reinterpret_cast<const uint4*>(src + j * 8);
        }
    };

    auto sts_regs = [&](int stage) {
        const uint32_t abase = sb + stage * STAGE_BYTES;
        const uint32_t bbase = abase + 128 * 128;
        #pragma unroll
        for (int j = 0; j < 8; j++) {
            const int m = msub + 16 * j;
            const uint32_t addr = abase + m * 128
                + ((((kq * 4) >> 3) ^ (m & 7)) << 4) + ((kq & 1) << 3);
            sts64(addr, pack2(af[j].x, af[j].y), pack2(af[j].z, af[j].w));
        }
        if constexpr (G1) {
            #pragma unroll
            for (int j = 0; j < 8; j++) {
                const float* f = &bw[j].x;
                #pragma unroll
                for (int q = 0; q < 4; q++) {
                    const int n = nq + q;
                    const uint32_t addr = bbase + n * 128
                        + ((j ^ (n & 7)) << 4) + (kk << 1);
                    sts16(addr, __half_as_ushort(__float2half_rn(f[q])));
                }
            }
        } else {
            #pragma unroll
            for (int j = 0; j < 4; j++) {
                const int chunk = bh * 4 + j;
                const uint32_t addr = bbase + bn * 128 + ((chunk ^ (bn & 7)) << 4);
                sts128(addr, bx[j]);
            }
        }
    };

    // ---- accumulators ----
    float c[2][8][4];
    #pragma unroll
    for (int mi = 0; mi < 2; mi++)
        #pragma unroll
        for (int nj = 0; nj < 8; nj++)
            #pragma unroll
            for (int q = 0; q < 4; q++) c[mi][nj][q] = 0.f;

    // ldmatrix lane geometry (precomputed)
    const int rowA  = warpM + (lane & 15);
    const int cpA   = lane >> 4;                       // A k-chunk part
    const int rowB7 = lane & 7;                        // rowB & 7
    const int rowBb = warpN + (lane & 7) + 8 * (lane >> 4);
    const int cpB   = (lane >> 3) & 1;

    auto compute = [&](int stage) {
        const uint32_t abase = sb + stage * STAGE_BYTES;
        const uint32_t bbase = abase + 128 * 128;
        #pragma unroll
        for (int ks = 0; ks < 4; ks++) {
            uint32_t a[2][4];
            #pragma unroll
            for (int mi = 0; mi < 2; mi++)
                ldsm_x4(a[mi], abase + (rowA + mi * 16) * 128
                        + (((ks * 2 + cpA) ^ (rowA & 7)) << 4));
            uint32_t b[4][4];
            #pragma unroll
            for (int nbp = 0; nbp < 4; nbp++)
                ldsm_x4(b[nbp], bbase + (rowBb + nbp * 16) * 128
                        + (((ks * 2 + cpB) ^ rowB7) << 4));
            #pragma unroll
            for (int mi = 0; mi < 2; mi++)
                #pragma unroll
                for (int nbp = 0; nbp < 4; nbp++) {
                    mma16816(c[mi][nbp * 2 + 0], a[mi], b[nbp][0], b[nbp][1]);
                    mma16816(c[mi][nbp * 2 + 1], a[mi], b[nbp][2], b[nbp][3]);
                }
        }
    };

    // ---- pipeline: 2-stage smem double buffer, regs one tile ahead ----
    load_regs(0);
    sts_regs(0);
    __syncthreads();
    if (iters > 1) load_regs(1);

    for (int i = 0; i < iters; i++) {
        if (i + 1 < iters) sts_regs((i + 1) & 1);
        __syncthreads();
        if (i + 2 < iters) load_regs(i + 2);
        compute(i & 1);
        __syncthreads();
    }

    // ---- epilogue ----
    const int erow = m0 + warpM + (lane >> 2);
    const int ecol = warpN + (lane & 3) * 2;
    #pragma unroll
    for (int mi = 0; mi < 2; mi++) {
        #pragma unroll
        for (int nj = 0; nj < 8; nj++) {
            const int r = erow + mi * 16;
            const int n = ecol + nj * 8;
            const float* cc = c[mi][nj];
            if constexpr (G1) {
                g_xT[(long)n * N_ROWS + r]           = __half_as_ushort(__float2half_rn(cc[0]));
                g_xT[(long)(n + 1) * N_ROWS + r]     = __half_as_ushort(__float2half_rn(cc[1]));
                g_xT[(long)n * N_ROWS + r + 8]       = __half_as_ushort(__float2half_rn(cc[2]));
                g_xT[(long)(n + 1) * N_ROWS + r + 8] = __half_as_ushort(__float2half_rn(cc[3]));
            } else {
                *reinterpret_cast<float2*>(Out + (long)r * NT + n)       = make_float2(cc[0], cc[1]);
                *reinterpret_cast<float2*>(Out + (long)(r + 8) * NT + n) = make_float2(cc[2], cc[3]);
            }
        }
    }
}

// ============================================================================
extern "C" void kernel_launch(void* const* d_in, const int* in_sizes, int n_in,
                              void* d_out, int out_size)
{
    const float* inputs = nullptr;
    const float* adj = nullptr;
    const float* w = nullptr;
    for (int i = 0; i < n_in; i++) {
        if (in_sizes[i] == N_ROWS * D_IN)        inputs = (const float*)d_in[i];
        else if (in_sizes[i] == N_ROWS * N_ROWS) adj    = (const float*)d_in[i];
        else if (in_sizes[i] == D_IN * D_OUT)    w      = (const float*)d_in[i];
    }
    float* out = (float*)d_out;

    cudaFuncSetAttribute(gcn_gemm<true>,
                         cudaFuncAttributeMaxDynamicSharedMemorySize, SMEM_TOTAL);
    cudaFuncSetAttribute(gcn_gemm<false>,
                         cudaFuncAttributeMaxDynamicSharedMemorySize, SMEM_TOTAL);

    // GEMM1: xT = (inputs @ W)^T  (fp16 scratch)
    gcn_gemm<true><<<N_ROWS / MT, 256, SMEM_TOTAL>>>(inputs, w, nullptr, D_IN, D_IN);
    // GEMM2: out = adj @ x
    gcn_gemm<false><<<N_ROWS / MT, 256, SMEM_TOTAL>>>(adj, nullptr, out, N_ROWS, N_ROWS);
}

// round 7
// speedup vs baseline: 1.0781x; 1.0781x over previous
#include <cuda_runtime.h>
#include <cuda_fp16.h>
#include <cstdint>

// ============================================================================
// GraphConvolutionSparse: out = adj @ (inputs @ W)
//   inputs [16384, 512] f32, adj [16384, 16384] f32, W [512, 128] f32
// sm_80-class ldmatrix + mma.sync.m16n8k16 (fp16 in, fp32 accum).
//   GEMM1: xT = (inputs @ W)^T  fp16 -> __device__ scratch
//   GEMM2: out = adj @ x, B = xT K-major
// R7: MT=64 (grid 256, 2 CTAs/SM), 3-stage ring, ONE barrier/iter,
//     cp.async for the fp16 B tile in GEMM2.
// ============================================================================

#define N_ROWS 16384
#define D_IN   512
#define D_OUT  128

#define MT 64
#define NT 128
#define KT 64
#define NSTAGE 3
#define A_BYTES (MT * 128)                   // 64 rows x 128B fp16 = 8KB
#define B_BYTES (NT * 128)                   // 128 rows x 128B fp16 = 16KB
#define STAGE_BYTES (A_BYTES + B_BYTES)      // 24KB
#define SMEM_TOTAL (NSTAGE * STAGE_BYTES)    // 72KB

__device__ unsigned short g_xT[D_OUT * N_ROWS];   // x transposed, fp16 bits

// ---------------- helpers ----------------
static __device__ __forceinline__ uint32_t smem_u32(const void* p) {
    uint32_t a;
    asm("{ .reg .u64 t; cvta.to.shared.u64 t, %1; cvt.u32.u64 %0, t; }"
        : "=r"(a) : "l"(p));
    return a;
}
static __device__ __forceinline__ uint32_t pack2(float lo, float hi) {
    __half2 h = __floats2half2_rn(lo, hi);
    return *reinterpret_cast<uint32_t*>(&h);
}
static __device__ __forceinline__ void sts64(uint32_t a, uint32_t u0, uint32_t u1) {
    asm volatile("st.shared.v2.b32 [%0], {%1,%2};" :: "r"(a), "r"(u0), "r"(u1) : "memory");
}
static __device__ __forceinline__ void sts16(uint32_t a, unsigned short h) {
    asm volatile("st.shared.u16 [%0], %1;" :: "r"(a), "h"(h) : "memory");
}
static __device__ __forceinline__ void cp16(uint32_t dst, const void* src) {
    asm volatile("cp.async.cg.shared.global [%0], [%1], 16;"
                 :: "r"(dst), "l"(src) : "memory");
}
static __device__ __forceinline__ void cp_commit() {
    asm volatile("cp.async.commit_group;" ::: "memory");
}
static __device__ __forceinline__ void cp_wait1() {
    asm volatile("cp.async.wait_group 1;" ::: "memory");
}
static __device__ __forceinline__ void ldsm_x4(uint32_t* r, uint32_t addr) {
    asm volatile("ldmatrix.sync.aligned.m8n8.x4.shared.b16 {%0,%1,%2,%3}, [%4];"
                 : "=r"(r[0]), "=r"(r[1]), "=r"(r[2]), "=r"(r[3]) : "r"(addr));
}
static __device__ __forceinline__ void mma16816(float* c, const uint32_t* a,
                                                uint32_t b0, uint32_t b1) {
    asm volatile(
        "mma.sync.aligned.m16n8k16.row.col.f32.f16.f16.f32 "
        "{%0,%1,%2,%3}, {%4,%5,%6,%7}, {%8,%9}, {%0,%1,%2,%3};"
        : "+f"(c[0]), "+f"(c[1]), "+f"(c[2]), "+f"(c[3])
        : "r"(a[0]), "r"(a[1]), "r"(a[2]), "r"(a[3]), "r"(b0), "r"(b1));
}

// ============================================================================
// G1=true : B = W fp32 [K,128] (reg-staged + cvt), epilogue -> g_xT transposed
// G1=false: B = g_xT fp16 (cp.async),              epilogue -> Out f32
// CTA tile 64x128, K-tile 64, 8 warps (2M x 4N), warp tile 32x32.
// ============================================================================
template <bool G1>
__global__ void __launch_bounds__(256, 2)
gcn_gemm(const float* __restrict__ A, const float* __restrict__ W,
         float* __restrict__ Out, int K, int lda)
{
    extern __shared__ char smem[];
    const uint32_t sb = smem_u32(smem);
    const int tid = threadIdx.x;
    const int lane = tid & 31;
    const int wid = tid >> 5;
    const int m0 = blockIdx.x * MT;
    const int warpM = (wid & 1) * 32;     // 2 warps along M
    const int warpN = (wid >> 1) * 32;    // 4 warps along N
    const int iters = K / KT;

    // ---- staging ----
    float4 af[4];      // A tile: 64 rows x 64 f32 / 256 thr = 4 float4
    float4 bw[8];      // G1 only: W gather

    const int msub = tid >> 4;            // 0..15, rows msub + 16*j
    const int kq   = tid & 15;            // float4 slot in 64-f32 row
    const int bn = tid >> 1;              // 0..127 (G2 B row)
    const int bh = tid & 1;
    const int nq = (tid & 31) * 4;        // G1 W gather
    const int kk = tid >> 5;

    auto load_regs = [&](int i) {
        const long k0 = (long)i * KT;
        #pragma unroll
        for (int j = 0; j < 4; j++) {
            const int m = msub + 16 * j;
            af[j] = *reinterpret_cast<const float4*>(A + (long)(m0 + m) * lda + k0 + kq * 4);
        }
        if constexpr (G1) {
            #pragma unroll
            for (int j = 0; j < 8; j++) {
                const long k = k0 + kk + 8 * j;
                bw[j] = *reinterpret_cast<const float4*>(W + k * 128 + nq);
            }
        }
    };

    auto produce = [&](int i) {           // stage = i % NSTAGE
        const int stage = i % NSTAGE;
        const uint32_t abase = sb + stage * STAGE_BYTES;
        const uint32_t bbase = abase + A_BYTES;
        #pragma unroll
        for (int j = 0; j < 4; j++) {
            const int m = msub + 16 * j;
            const uint32_t addr = abase + m * 128
                + ((((kq * 4) >> 3) ^ (m & 7)) << 4) + ((kq & 1) << 3);
            sts64(addr, pack2(af[j].x, af[j].y), pack2(af[j].z, af[j].w));
        }
        if constexpr (G1) {
            #pragma unroll
            for (int j = 0; j < 8; j++) {
                const float* f = &bw[j].x;
                #pragma unroll
                for (int q = 0; q < 4; q++) {
                    const int n = nq + q;
                    const uint32_t addr = bbase + n * 128
                        + ((j ^ (n & 7)) << 4) + (kk << 1);
                    sts16(addr, __half_as_ushort(__float2half_rn(f[q])));
                }
            }
        } else {
            const long k0 = (long)i * KT;
            const unsigned short* src = g_xT + (long)bn * N_ROWS + k0;
            #pragma unroll
            for (int j = 0; j < 4; j++) {
                const int chunk = bh * 4 + j;
                cp16(bbase + bn * 128 + ((chunk ^ (bn & 7)) << 4), src + chunk * 8);
            }
        }
    };

    // ---- accumulators ----
    float c[2][4][4];
    #pragma unroll
    for (int mi = 0; mi < 2; mi++)
        #pragma unroll
        for (int nj = 0; nj < 4; nj++)
            #pragma unroll
            for (int q = 0; q < 4; q++) c[mi][nj][q] = 0.f;

    // ldmatrix lane geometry
    const int rowA  = warpM + (lane & 15);
    const int cpA   = lane >> 4;
    const int rowBb = warpN + (lane & 7) + 8 * (lane >> 4);
    const int rowB7 = rowBb & 7;
    const int cpB   = (lane >> 3) & 1;

    auto compute = [&](int i) {
        const int stage = i % NSTAGE;
        const uint32_t abase = sb + stage * STAGE_BYTES;
        const uint32_t bbase = abase + A_BYTES;
        #pragma unroll
        for (int ks = 0; ks < 4; ks++) {
            uint32_t a[2][4];
            #pragma unroll
            for (int mi = 0; mi < 2; mi++)
                ldsm_x4(a[mi], abase + (rowA + mi * 16) * 128
                        + (((ks * 2 + cpA) ^ (rowA & 7)) << 4));
            uint32_t b[2][4];
            #pragma unroll
            for (int nbp = 0; nbp < 2; nbp++)
                ldsm_x4(b[nbp], bbase + (rowBb + nbp * 16) * 128
                        + (((ks * 2 + cpB) ^ rowB7) << 4));
            #pragma unroll
            for (int mi = 0; mi < 2; mi++)
                #pragma unroll
                for (int nbp = 0; nbp < 2; nbp++) {
                    mma16816(c[mi][nbp * 2 + 0], a[mi], b[nbp][0], b[nbp][1]);
                    mma16816(c[mi][nbp * 2 + 1], a[mi], b[nbp][2], b[nbp][3]);
                }
        }
    };

    // ---- pipeline: 3-stage ring, one barrier per iteration ----
    load_regs(0);
    produce(0);
    if constexpr (!G1) cp_commit();
    if (iters > 1) load_regs(1);

    for (int i = 0; i < iters; i++) {
        if (i + 1 < iters) produce(i + 1);         // af holds tile i+1
        if constexpr (!G1) cp_commit();            // dense group numbering
        if (i + 2 < iters) load_regs(i + 2);       // LDGs overlap compute
        if constexpr (!G1) cp_wait1();             // B(i) landed (this thread)
        __syncthreads();                           // all threads' stage-i data visible
        compute(i);
    }

    // ---- epilogue ----
    const int erow = m0 + warpM + (lane >> 2);
    const int ecol = warpN + (lane & 3) * 2;
    #pragma unroll
    for (int mi = 0; mi < 2; mi++) {
        #pragma unroll
        for (int nj = 0; nj < 4; nj++) {
            const int r = erow + mi * 16;
            const int n = ecol + nj * 8;
            const float* cc = c[mi][nj];
            if constexpr (G1) {
                g_xT[(long)n * N_ROWS + r]           = __half_as_ushort(__float2half_rn(cc[0]));
                g_xT[(long)(n + 1) * N_ROWS + r]     = __half_as_ushort(__float2half_rn(cc[1]));
                g_xT[(long)n * N_ROWS + r + 8]       = __half_as_ushort(__float2half_rn(cc[2]));
                g_xT[(long)(n + 1) * N_ROWS + r + 8] = __half_as_ushort(__float2half_rn(cc[3]));
            } else {
                *reinterpret_cast<float2*>(Out + (long)r * NT + n)       = make_float2(cc[0], cc[1]);
                *reinterpret_cast<float2*>(Out + (long)(r + 8) * NT + n) = make_float2(cc[2], cc[3]);
            }
        }
    }
}

// ============================================================================
extern "C" void kernel_launch(void* const* d_in, const int* in_sizes, int n_in,
                              void* d_out, int out_size)
{
    const float* inputs = nullptr;
    const float* adj = nullptr;
    const float* w = nullptr;
    for (int i = 0; i < n_in; i++) {
        if (in_sizes[i] == N_ROWS * D_IN)        inputs = (const float*)d_in[i];
        else if (in_sizes[i] == N_ROWS * N_ROWS) adj    = (const float*)d_in[i];
        else if (in_sizes[i] == D_IN * D_OUT)    w      = (const float*)d_in[i];
    }
    float* out = (float*)d_out;

    cudaFuncSetAttribute(gcn_gemm<true>,
                         cudaFuncAttributeMaxDynamicSharedMemorySize, SMEM_TOTAL);
    cudaFuncSetAttribute(gcn_gemm<false>,
                         cudaFuncAttributeMaxDynamicSharedMemorySize, SMEM_TOTAL);

    // GEMM1: xT = (inputs @ W)^T  (fp16 scratch)
    gcn_gemm<true><<<N_ROWS / MT, 256, SMEM_TOTAL>>>(inputs, w, nullptr, D_IN, D_IN);
    // GEMM2: out = adj @ x
    gcn_gemm<false><<<N_ROWS / MT, 256, SMEM_TOTAL>>>(adj, nullptr, out, N_ROWS, N_ROWS);
}